// round 17
// baseline (speedup 1.0000x reference)
#include <cuda_runtime.h>

// ---------------- problem constants ----------------
#define KCLS 20
#define HH   480
#define WW   640
#define NPIX (HH * WW)           // 307200
#define NBATCH 4
#define FC   512
#define FH   30
#define FW   40
#define FHW  (FH * FW)           // 1200
#define NBOX 5
#define COUNT_THRESH 10000
#define XELEMS ((long long)(NBOX + 1) * NBATCH * FC * FHW)   // 14,745,600

#define QW 41                    // padded vq row stride (float4 units)

// ---------------- device scratch (zero-init neutral; tail resets) --------------
__device__ int      g_cnt[KCLS];
__device__ unsigned g_xlo[KCLS];        // coarse-x (x>>4) bits 0..31
__device__ unsigned g_xhi[KCLS];        // coarse-x bits 32..39
__device__ unsigned g_ym[KCLS];         // coarse-y (y>>4) bits 0..29
__device__ unsigned g_done;
__device__ int      g_node[NBOX][4];    // x0, y0, cw, ch
// precomputed interp tables (overwritten every launch before k_build reads them)
__device__ int      g_xi[NBOX][FW];     // x0 + xa
__device__ float    g_xf[NBOX][FW];     // fx
__device__ int      g_yi[NBOX][FH];     // (y0 + ya) * QW
__device__ float    g_yf[NBOX][FH];     // fy

// ------- kernel 1: argmax(K=20) of batch 3 + stats + fused tail ---------------
// f4 loads (4 px/thread), 300 blocks x 256. Tail block: selection + tables +
// pool/scalars + stat reset.
__global__ void k_stats(const float* __restrict__ seg,
                        float* __restrict__ out, const float* __restrict__ pool,
                        int pool_n, int x_off) {
    __shared__ int      s_cnt[KCLS];
    __shared__ unsigned s_xlo[KCLS], s_xhi[KCLS], s_ym[KCLS];
    __shared__ int      s_last;
    int t = threadIdx.x;
    if (t < KCLS) { s_cnt[t] = 0; s_xlo[t] = 0; s_xhi[t] = 0; s_ym[t] = 0; }
    __syncthreads();

    int p4 = blockIdx.x * blockDim.x + t;           // quad-pixel index
    const float4* base = (const float4*)(seg + (long long)3 * KCLS * NPIX);

    float b0 = -1e30f, b1 = -1e30f, b2 = -1e30f, b3 = -1e30f;
    int   k0 = 0, k1 = 0, k2 = 0, k3 = 0;
#pragma unroll
    for (int k = 0; k < KCLS; k++) {
        float4 v = __ldg(base + k * (NPIX / 4) + p4);
        if (v.x > b0) { b0 = v.x; k0 = k; }
        if (v.y > b1) { b1 = v.y; k1 = k; }
        if (v.z > b2) { b2 = v.z; k2 = k; }
        if (v.w > b3) { b3 = v.w; k3 = k; }
    }

    int y  = p4 / (WW / 4);
    int xb = (p4 % (WW / 4)) * 4;
    int xc = xb >> 4;                       // all 4 quad pixels share this cell
    unsigned xbit  = (xc < 32) ? (1u << xc) : 0u;
    unsigned xbith = (xc < 32) ? 0u : (1u << (xc - 32));
    unsigned ybit  = 1u << (y >> 4);

    int ks[4] = {k0, k1, k2, k3};
#pragma unroll
    for (int i = 0; i < 4; i++) {
        int k = ks[i];
        atomicAdd(&s_cnt[k], 1);
        // dedup: racy read benign (OR idempotent); skips ~all repeats
        if (xbit)  { if (!(s_xlo[k] & xbit))  atomicOr(&s_xlo[k], xbit); }
        else       { if (!(s_xhi[k] & xbith)) atomicOr(&s_xhi[k], xbith); }
        if (!(s_ym[k] & ybit)) atomicOr(&s_ym[k], ybit);
    }
    __syncthreads();

    if (t < KCLS && s_cnt[t] > 0) {
        atomicAdd(&g_cnt[t], s_cnt[t]);
        if (s_xlo[t]) atomicOr(&g_xlo[t], s_xlo[t]);
        if (s_xhi[t]) atomicOr(&g_xhi[t], s_xhi[t]);
        atomicOr(&g_ym[t], s_ym[t]);
    }
    __syncthreads();

    if (t == 0) {
        __threadfence();
        unsigned done = atomicAdd(&g_done, 1u);
        s_last = (done == gridDim.x - 1) ? 1 : 0;
    }
    __syncthreads();
    if (!s_last) return;

    // ---------- tail block ----------
    if (t == 0) {
        int cand[KCLS], ccnt[KCLS];
        int m = 0, first_seen = -1;
        for (int k = 0; k < KCLS; k++) {
            int c = *(volatile int*)&g_cnt[k];
            if (c > 0) {
                if (first_seen < 0) first_seen = k;      // np.unique()[1:]
                else { cand[m] = k; ccnt[m] = c; m++; }
            }
        }
        bool used[KCLS];
        for (int i = 0; i < m; i++) used[i] = false;
        int selb[NBOX - 2];
        int selcnt = 0;
        for (int r = 0; r < m && selcnt < NBOX - 2; r++) {
            int best = -1;
            for (int j = 0; j < m; j++)
                if (!used[j] && (best < 0 || ccnt[j] > ccnt[best])) best = j;
            used[best] = true;
            if (ccnt[best] > COUNT_THRESH) selb[selcnt++] = cand[best];
        }
        for (int i = 0; i < selcnt; i++) {
            int k = selb[i];
            unsigned long long x64 =
                ((unsigned long long)(*(volatile unsigned*)&g_xhi[k]) << 32) |
                (*(volatile unsigned*)&g_xlo[k]);
            unsigned ym = *(volatile unsigned*)&g_ym[k];
            int x0 = __ffsll(x64) - 1;
            int x1 = 63 - __clzll(x64);
            int y0 = __ffs(ym) - 1;
            int y1 = 31 - __clz(ym);
            int cw = x1 - x0; if (cw < 1) cw = 1;
            int ch = y1 - y0; if (ch < 1) ch = 1;
            g_node[i][0] = x0; g_node[i][1] = y0;
            g_node[i][2] = cw; g_node[i][3] = ch;
        }
        const int bb[5][4] = {
            {FW / 4, FH / 4, 3 * FW / 4, 3 * FH / 4},
            {0, 0, FW / 3, FH},
            {0, 0, FW, FH / 3},
            {2 * FW / 3, 0, FW, FH},
            {0, 2 * FH / 3, FW, FH}};
        int need = NBOX - selcnt;
        for (int i = 0; i < need; i++) {
            int x0 = bb[i][0], y0 = bb[i][1];
            g_node[selcnt + i][0] = x0; g_node[selcnt + i][1] = y0;
            g_node[selcnt + i][2] = bb[i][2] - x0;
            g_node[selcnt + i][3] = bb[i][3] - y0;
        }
        if (x_off == pool_n + 2) {
            out[pool_n]     = (float)NBOX;     // 5
            out[pool_n + 1] = (float)NBATCH;   // 4
        }
        g_done = 0;
    }
    __syncthreads();   // g_node ready; stats fully read before reset below

    // parallel interp-table fill (reads g_node only)
    if (t < NBOX * FW) {                      // 200 x-entries
        int b = t / FW, w = t - b * FW;
        int x0 = g_node[b][0], cw = g_node[b][2];
        float s = ((float)w + 0.5f) * ((float)cw / (float)FW) - 0.5f;
        s = fminf(fmaxf(s, 0.0f), (float)(cw - 1));
        int xa = (int)s;
        g_xi[b][w] = x0 + xa;
        g_xf[b][w] = s - (float)xa;
    }
    if (t < NBOX * FH) {                      // 150 y-entries
        int b = t / FH, h = t - b * FH;
        int y0 = g_node[b][1], ch = g_node[b][3];
        float s = ((float)h + 0.5f) * ((float)ch / (float)FH) - 0.5f;
        s = fminf(fmaxf(s, 0.0f), (float)(ch - 1));
        int ya = (int)s;
        g_yi[b][h] = (y0 + ya) * QW;
        g_yf[b][h] = s - (float)ya;
    }
    // stat reset (neutral zero for next graph replay)
    if (t < KCLS) {
        g_cnt[t] = 0; g_xlo[t] = 0; g_xhi[t] = 0; g_ym[t] = 0;
    }
    // pool_x copy
    if (x_off >= pool_n)
        for (int i = t; i < pool_n; i += blockDim.x) out[i] = pool[i];
}

// ------- kernel 2: quad layout, 1 channel/block, table-driven params ----------
// vq[h][x] = (v[h][x], v[h][x+1], v[h+1][x], v[h+1][x+1]): all 4 taps = 1 LDS.128.
// grid (4, 512), block (20, 15), 19.7 KB smem -> 6 blocks/SM.
__global__ __launch_bounds__(300, 6) void k_build(float* __restrict__ out_x,
                                                  const float* __restrict__ feat) {
    __shared__ float4 vq[FH * QW];            // 30x41 float4 = 19.7 KB
    int n = blockIdx.x;                       // 0..3
    int c = blockIdx.y;                       // 0..511
    int tx = threadIdx.x;                     // 0..19
    int ty = threadIdx.y;                     // 0..14
    int tid = ty * 20 + tx;

    const float* src = feat + (n * FC + c) * FHW;

    // ---- stage vq (clamped neighbors; redundant LDGs are L1-hot) ----
#pragma unroll
    for (int jh = 0; jh < 2; jh++) {
#pragma unroll
        for (int jw = 0; jw < 2; jw++) {
            int h  = ty + 15 * jh, w = tx + 20 * jw;
            int hn = min(h + 1, FH - 1);
            int wn = min(w + 1, FW - 1);
            float a = __ldg(src + h  * FW + w);
            float b = __ldg(src + h  * FW + wn);
            float cc = __ldg(src + hn * FW + w);
            float d = __ldg(src + hn * FW + wn);
            vq[h * QW + w] = make_float4(a, b, cc, d);
        }
    }

    // ---- feat-copy plane (20+n), overlapped before sync ----
    {
        const float2* srcv = (const float2*)src;
        float2* dstv = (float2*)out_x + (((20 + n) * FC + c) * FHW >> 1);
        dstv[tid]       = __ldg(srcv + tid);
        dstv[tid + 300] = __ldg(srcv + tid + 300);
    }
    __syncthreads();

    // ---- 5 resize planes; params from precomputed tables (L1-hot broadcast) ----
    for (int b = 0; b < NBOX; b++) {
        int   gx0 = __ldg(&g_xi[b][2 * tx]);
        float fx0 = __ldg(&g_xf[b][2 * tx]);
        int   gx1 = __ldg(&g_xi[b][2 * tx + 1]);
        float fx1 = __ldg(&g_xf[b][2 * tx + 1]);
        float* dst = out_x + ((n * NBOX + b) * FC + c) * FHW;
#pragma unroll
        for (int hh = 0; hh < 2; hh++) {
            int h = ty + 15 * hh;
            int   ra = __ldg(&g_yi[b][h]);
            float fy = __ldg(&g_yf[b][h]);
            float4 q0 = vq[ra + gx0];
            float4 q1 = vq[ra + gx1];
            float ofy = 1.0f - fy;
            float t0 = (1.0f - fx0) * q0.x + fx0 * q0.y;
            float u0 = (1.0f - fx0) * q0.z + fx0 * q0.w;
            float t1 = (1.0f - fx1) * q1.x + fx1 * q1.y;
            float u1 = (1.0f - fx1) * q1.z + fx1 * q1.w;
            float2 pv;
            pv.x = ofy * t0 + fy * u0;
            pv.y = ofy * t1 + fy * u1;
            ((float2*)(dst + h * FW))[tx] = pv;
        }
    }
}

// ---------------- launcher: 2 kernels ----------------
extern "C" void kernel_launch(void* const* d_in, const int* in_sizes, int n_in,
                              void* d_out, int out_size) {
    const float* seg  = (const float*)d_in[0];
    const float* feat = (const float*)d_in[1];
    const float* pool = (const float*)d_in[2];
    float* out = (float*)d_out;

    long long x_off_ll = (long long)out_size - XELEMS;
    if (x_off_ll < 0) x_off_ll = 0;
    int x_off = (int)x_off_ll;
    int pool_n = (n_in > 2) ? in_sizes[2] : 0;
    if (pool_n > x_off) pool_n = x_off;

    k_stats<<<NPIX / 4 / 256, 256>>>(seg, out, pool, pool_n, x_off);
    dim3 grid(NBATCH, FC);                    // (4, 512) = 2048 blocks
    dim3 blk(20, 15);
    k_build<<<grid, blk>>>(out + x_off, feat);
}